// round 8
// baseline (speedup 1.0000x reference)
#include <cuda_runtime.h>

// Double-softmax attention, fp32. B=4,H=8,N=2048,D=64.
//   L = Q K^T * scale ; mask = softmax(2L) ; attn = softmax(L*mask) ; O = attn V
// One CTA = 16 query rows of one (b,h), 512 threads (16 warps).
// P1: t = L*exp(2L) into SMEM panel, Z1 folded.  P3: fused exp2 convert + O = P V.

#define NKEYS   2048
#define DIM     64
#define MQ      16
#define CHUNK   256
#define NCHUNK  8
#define THREADS 512
#define NBLK_Q  128

#define S_FLOATS   (MQ * NKEYS)     // 32768
#define KT_FLOATS  (CHUNK * DIM)    // 16384 (K tile; P3 scratch)
#define QS_FLOATS  (MQ * DIM)       // 1024
#define SMEM_FLOATS (S_FLOATS + KT_FLOATS + QS_FLOATS + 128 + 16 + 16)
#define SMEM_BYTES  (SMEM_FLOATS * 4)

typedef unsigned long long u64;

__device__ __forceinline__ u64 pk2(float lo, float hi) {
    u64 r; asm("mov.b64 %0,{%1,%2};" : "=l"(r) : "f"(lo), "f"(hi)); return r;
}
__device__ __forceinline__ void upk2(u64 a, float& lo, float& hi) {
    asm("mov.b64 {%0,%1},%2;" : "=f"(lo), "=f"(hi) : "l"(a));
}
__device__ __forceinline__ void ffma2(u64& d, u64 a, u64 b) {
    asm("fma.rn.f32x2 %0,%1,%2,%0;" : "+l"(d) : "l"(a), "l"(b));
}
__device__ __forceinline__ float ex2f(float x) {
    float r; asm("ex2.approx.f32 %0,%1;" : "=f"(r) : "f"(x)); return r;
}

__global__ __launch_bounds__(THREADS, 1)
void dsmax_attn_kernel(const float* __restrict__ Q,
                       const float* __restrict__ K,
                       const float* __restrict__ V,
                       const float* __restrict__ scalep,
                       float* __restrict__ O)
{
    extern __shared__ float smem[];
    float* S      = smem;                       // [MQ][NKEYS]  t -> P'
    float* Kt     = S + S_FLOATS;               // [CHUNK][DIM] swizzled K tile / scratch
    float* Qs     = Kt + KT_FLOATS;             // [MQ][DIM] swizzled Q
    float* zscr   = Qs + QS_FLOATS;             // [16 warps][8]
    float* c2s    = zscr + 128;                 // [16] log2e / Z1
    float* invZ2s = c2s + 16;                   // [16]

    const int tid  = threadIdx.x;
    const int warp = tid >> 5, lane = tid & 31;
    const int bh   = blockIdx.x >> 7;
    const int qb   = (blockIdx.x & (NBLK_Q - 1)) * MQ;
    const float scale = *scalep;

    const float* Qb = Q + ((size_t)bh * NKEYS + qb) * DIM;
    const float* Kb = K + (size_t)bh * NKEYS * DIM;
    const float* Vb = V + (size_t)bh * NKEYS * DIM;
    float*       Ob = O + ((size_t)bh * NKEYS + qb) * DIM;

    // ---- stage Q swizzled: col16 = d4 ^ ((q>>1)&3) ----
    if (tid < 256) {
        const int q = tid >> 4, d4 = tid & 15;
        *(float4*)&Qs[q * DIM + ((d4 ^ ((q >> 1) & 3)) << 2)] = ((const float4*)Qb)[tid];
    }

    // ---- prefetch K chunk 0 ----
    float4 pf[8];
    {
        const float4* src = (const float4*)Kb;
        #pragma unroll
        for (int i = 0; i < 8; i++) pf[i] = src[i * THREADS + tid];
    }
    __syncthreads();

    // ================= Phase 1: t = L*exp(2L), Z1 partials =================
    // kg: 64 key-groups of 4; qg: 8 q-groups of 2
    const int kg  = (tid & 7) | (((tid >> 5) & 7) << 3);
    const int qg  = ((tid >> 3) & 3) | ((tid >> 8) << 2);
    const int ksw = kg & 7;
    const int qsw = qg & 3;          // == ((2qg)>>1)&3
    float z1p[2] = {0.f, 0.f};

    for (int c = 0; c < NCHUNK; c++) {
        // commit K chunk, swizzle col16 = d4 ^ ((key>>2)&7)
        #pragma unroll
        for (int i = 0; i < 8; i++) {
            int g   = i * THREADS + tid;
            int key = g >> 4;
            int d4  = g & 15;
            *(float4*)&Kt[key * DIM + ((d4 ^ ((key >> 2) & 7)) << 2)] = pf[i];
        }
        __syncthreads();
        if (c + 1 < NCHUNK) {
            const float4* src = (const float4*)(Kb + (size_t)(c + 1) * CHUNK * DIM);
            #pragma unroll
            for (int i = 0; i < 8; i++) pf[i] = src[i * THREADS + tid];
        }

        u64 acc[2][4];
        #pragma unroll
        for (int a = 0; a < 2; a++)
            #pragma unroll
            for (int b = 0; b < 4; b++) acc[a][b] = 0ull;

        #pragma unroll
        for (int d4 = 0; d4 < 16; d4++) {
            const int kco = (d4 ^ ksw) << 2;
            ulonglong2 kv[4];
            #pragma unroll
            for (int j = 0; j < 4; j++)
                kv[j] = *(const ulonglong2*)(Kt + (4 * kg + j) * DIM + kco);
            const int qco = (d4 ^ qsw) << 2;
            #pragma unroll
            for (int jq = 0; jq < 2; jq++) {
                ulonglong2 qv = *(const ulonglong2*)(Qs + (2 * qg + jq) * DIM + qco);
                #pragma unroll
                for (int j = 0; j < 4; j++) {
                    ffma2(acc[jq][j], qv.x, kv[j].x);
                    ffma2(acc[jq][j], qv.y, kv[j].y);
                }
            }
        }

        const int key0 = c * CHUNK + 4 * kg;
        #pragma unroll
        for (int jq = 0; jq < 2; jq++) {
            float t[4];
            #pragma unroll
            for (int j = 0; j < 4; j++) {
                float lo, hi; upk2(acc[jq][j], lo, hi);
                float L  = (lo + hi) * scale;
                float e2 = __expf(2.0f * L);
                z1p[jq] += e2;
                t[j] = L * e2;
            }
            *(float4*)&S[(size_t)(2 * qg + jq) * NKEYS + key0] =
                make_float4(t[0], t[1], t[2], t[3]);
        }
        __syncthreads();
    }

    // ---- Z1 reduce: over kg-low lanes, then across warps ----
    #pragma unroll
    for (int jq = 0; jq < 2; jq++) {
        float v = z1p[jq];
        v += __shfl_xor_sync(0xffffffffu, v, 1);
        v += __shfl_xor_sync(0xffffffffu, v, 2);
        v += __shfl_xor_sync(0xffffffffu, v, 4);
        if ((lane & 7) == 0) zscr[warp * 8 + (lane >> 3) * 2 + jq] = v;
    }
    __syncthreads();
    if (tid < 16) {
        const int q = tid;
        const int wbase = (q >> 3) * 8;
        const int slot  = ((q >> 1) & 3) * 2 + (q & 1);
        float z1 = 0.f;
        #pragma unroll
        for (int w = 0; w < 8; w++) z1 += zscr[(wbase + w) * 8 + slot];
        c2s[q] = 1.4426950408889634f / z1;        // log2e / Z1
    }
    __syncthreads();

    // ================= Phase 3: fused convert + O = P V =================
    const int d2    = lane;              // dcols {d2, d2+32}
    const int slice = warp;              // 16 keys per chunk per slice
    const float c2q = c2s[warp];         // conversion row = warp

    u64 acc0[MQ], acc1[MQ];
    #pragma unroll
    for (int q = 0; q < MQ; q++) { acc0[q] = 0ull; acc1[q] = 0ull; }
    float z2 = 0.f;

    float vA[2][8];

#define LOADV(BUF, C, B)                                                    \
    {                                                                       \
        const float* vp = Vb + (size_t)((C) * CHUNK + slice * 16 + (B) * 8) * DIM + d2; \
        _Pragma("unroll")                                                   \
        for (int j = 0; j < 8; j++) {                                       \
            BUF[0][j] = vp[j * DIM];                                        \
            BUF[1][j] = vp[j * DIM + 32];                                   \
        }                                                                   \
    }

#define MMAB(BUF, C, B)                                                     \
    {                                                                       \
        u64 vp0[4], vp1[4];                                                 \
        _Pragma("unroll")                                                   \
        for (int j = 0; j < 4; j++) {                                       \
            vp0[j] = pk2(BUF[0][2 * j], BUF[0][2 * j + 1]);                 \
            vp1[j] = pk2(BUF[1][2 * j], BUF[1][2 * j + 1]);                 \
        }                                                                   \
        const float* pbase = S + (C) * CHUNK + slice * 16 + (B) * 8;        \
        _Pragma("unroll")                                                   \
        for (int q = 0; q < MQ; q++) {                                      \
            const float* prow = pbase + (size_t)q * NKEYS;                  \
            ulonglong2 pA = *(const ulonglong2*)(prow);                     \
            ulonglong2 pB = *(const ulonglong2*)(prow + 4);                 \
            ffma2(acc0[q], pA.x, vp0[0]);                                   \
            ffma2(acc0[q], pA.y, vp0[1]);                                   \
            ffma2(acc0[q], pB.x, vp0[2]);                                   \
            ffma2(acc0[q], pB.y, vp0[3]);                                   \
            ffma2(acc1[q], pA.x, vp1[0]);                                   \
            ffma2(acc1[q], pA.y, vp1[1]);                                   \
            ffma2(acc1[q], pB.x, vp1[2]);                                   \
            ffma2(acc1[q], pB.y, vp1[3]);                                   \
        }                                                                   \
    }

    for (int c = 0; c < NCHUNK; c++) {
        LOADV(vA, c, 0);
        // convert chunk c of row `warp`: P = exp2(t * log2e/Z1), accumulate Z2
        {
            float4* p = (float4*)(S + (size_t)warp * NKEYS + c * CHUNK) + lane;
            #pragma unroll
            for (int i = 0; i < 2; i++) {
                float4 x = p[i * 32];
                x.x = ex2f(x.x * c2q);
                x.y = ex2f(x.y * c2q);
                x.z = ex2f(x.z * c2q);
                x.w = ex2f(x.w * c2q);
                z2 += (x.x + x.y) + (x.z + x.w);
                p[i * 32] = x;
            }
        }
        __syncthreads();           // chunk c conversions visible to all warps
        MMAB(vA, c, 0);
        LOADV(vA, c, 1);
        MMAB(vA, c, 1);
        // next iter converts chunk c+1 only; no trailing barrier needed
    }

    // ---- Z2 finalize: full-warp reduce per row ----
    {
        float v = z2;
        #pragma unroll
        for (int o = 16; o > 0; o >>= 1) v += __shfl_xor_sync(0xffffffffu, v, o);
        if (lane == 0) invZ2s[warp] = 1.0f / v;
    }
    __syncthreads();

    // ---- cross-slice reduction through Kt (dead): scratch[slice][q][64] ----
    float* scratch = Kt;
    #pragma unroll
    for (int q = 0; q < MQ; q++) {
        float lo, hi, r0, r1;
        upk2(acc0[q], lo, hi); r0 = (lo + hi) * invZ2s[q];
        upk2(acc1[q], lo, hi); r1 = (lo + hi) * invZ2s[q];
        scratch[(slice * MQ + q) * 64 + d2]      = r0;
        scratch[(slice * MQ + q) * 64 + d2 + 32] = r1;
    }
    __syncthreads();

    #pragma unroll
    for (int e = tid; e < MQ * DIM; e += THREADS) {
        int q = e >> 6, d = e & 63;
        float r = 0.f;
        #pragma unroll
        for (int s2 = 0; s2 < 16; s2++)
            r += scratch[(s2 * MQ + q) * 64 + d];
        Ob[(size_t)q * DIM + d] = r;
    }
}

extern "C" void kernel_launch(void* const* d_in, const int* in_sizes, int n_in,
                              void* d_out, int out_size)
{
    const float* q     = (const float*)d_in[0];
    const float* k     = (const float*)d_in[1];
    const float* v     = (const float*)d_in[2];
    const float* scale = (const float*)d_in[3];
    float* out = (float*)d_out;

    cudaFuncSetAttribute(dsmax_attn_kernel,
                         cudaFuncAttributeMaxDynamicSharedMemorySize, SMEM_BYTES);

    dim3 grid(32 * NBLK_Q);   // (B*H) * query-blocks = 4096
    dsmax_attn_kernel<<<grid, THREADS, SMEM_BYTES>>>(q, k, v, scale, out);
}

// round 9
// speedup vs baseline: 1.1232x; 1.1232x over previous
#include <cuda_runtime.h>

// Double-softmax attention, fp32. B=4,H=8,N=2048,D=64.
//   L = Q K^T * scale ; mask = softmax(2L) ; attn = softmax(L*mask) ; O = attn V
// One CTA = 16 query rows of one (b,h), 256 threads, 1 CTA/SM (no reg cap).
// P1: t = L*exp(2L) into SMEM panel, Z1 folded; double-buffered K tile,
//     one barrier per 128-key chunk.
// P2: single conversion sweep P = exp2(t * log2e/Z1), Z2 fused. One barrier.
// P3: barrier-free O = P V with V streamed from L2, double-buffered in regs.

#define NKEYS   2048
#define DIM     64
#define MQ      16
#define CHUNK   128
#define NCHUNK  16
#define THREADS 256
#define NBLK_Q  128

#define S_FLOATS    (MQ * NKEYS)       // 32768
#define KTBUF       (CHUNK * DIM)      // 8192 per buffer
#define KT_FLOATS   (2 * KTBUF)        // 16384 (double buffer; P3 scratch)
#define QS_FLOATS   (MQ * DIM)         // 1024
#define SMEM_FLOATS (S_FLOATS + KT_FLOATS + QS_FLOATS + 64 + 16 + 16)
#define SMEM_BYTES  (SMEM_FLOATS * 4)  // ~201 KB

typedef unsigned long long u64;

__device__ __forceinline__ u64 pk2(float lo, float hi) {
    u64 r; asm("mov.b64 %0,{%1,%2};" : "=l"(r) : "f"(lo), "f"(hi)); return r;
}
__device__ __forceinline__ void upk2(u64 a, float& lo, float& hi) {
    asm("mov.b64 {%0,%1},%2;" : "=f"(lo), "=f"(hi) : "l"(a));
}
__device__ __forceinline__ void ffma2(u64& d, u64 a, u64 b) {
    asm("fma.rn.f32x2 %0,%1,%2,%0;" : "+l"(d) : "l"(a), "l"(b));
}
__device__ __forceinline__ float ex2f(float x) {
    float r; asm("ex2.approx.f32 %0,%1;" : "=f"(r) : "f"(x)); return r;
}

__global__ __launch_bounds__(THREADS, 1)
void dsmax_attn_kernel(const float* __restrict__ Q,
                       const float* __restrict__ K,
                       const float* __restrict__ V,
                       const float* __restrict__ scalep,
                       float* __restrict__ O)
{
    extern __shared__ float smem[];
    float* S      = smem;                       // [MQ][NKEYS]  t -> P'
    float* Kt     = S + S_FLOATS;               // 2 x [CHUNK][DIM] swizzled; P3 scratch
    float* Qs     = Kt + KT_FLOATS;             // [MQ][DIM] swizzled Q
    float* zscr   = Qs + QS_FLOATS;             // [8 warps][8]
    float* c2s    = zscr + 64;                  // [16] log2e / Z1
    float* invZ2s = c2s + 16;                   // [16]

    const int tid  = threadIdx.x;
    const int warp = tid >> 5, lane = tid & 31;
    const int bh   = blockIdx.x >> 7;
    const int qb   = (blockIdx.x & (NBLK_Q - 1)) * MQ;
    const float scale = *scalep;

    const float* Qb = Q + ((size_t)bh * NKEYS + qb) * DIM;
    const float* Kb = K + (size_t)bh * NKEYS * DIM;
    const float* Vb = V + (size_t)bh * NKEYS * DIM;
    float*       Ob = O + ((size_t)bh * NKEYS + qb) * DIM;

    // ---- stage Q swizzled: col16 = d4 ^ ((q>>1)&3) ----
    {
        const int q = tid >> 4, d4 = tid & 15;
        *(float4*)&Qs[q * DIM + ((d4 ^ ((q >> 1) & 3)) << 2)] = ((const float4*)Qb)[tid];
    }

    // ---- prefetch K chunk 0 ----
    float4 pf[8];
    {
        const float4* src = (const float4*)Kb;
        #pragma unroll
        for (int i = 0; i < 8; i++) pf[i] = src[i * THREADS + tid];
    }
    __syncthreads();   // Qs visible

    // ================= Phase 1: t = L*exp(2L), Z1 partials =================
    // 128 keys x 16 q per chunk; thread tile 4 keys x 2 q.
    // kg: 32 key-groups of 4 (warp covers 8 via lane&7); qg: 8 q-groups of 2.
    const int kg  = (tid & 7) | (((tid >> 5) & 3) << 3);
    const int qg  = ((tid >> 3) & 3) | ((tid >> 7) << 2);
    const int ksw = kg & 7;
    const int qsw = qg & 3;
    float z1p[2] = {0.f, 0.f};

    for (int c = 0; c < NCHUNK; c++) {
        float* Ktb = Kt + (c & 1) * KTBUF;
        // commit chunk c (WAR on this buffer covered by barrier of iter c-1)
        #pragma unroll
        for (int i = 0; i < 8; i++) {
            int g   = i * THREADS + tid;
            int key = g >> 4;
            int d4  = g & 15;
            *(float4*)&Ktb[key * DIM + ((d4 ^ ((key >> 2) & 7)) << 2)] = pf[i];
        }
        __syncthreads();                     // chunk c visible; compute may begin
        if (c + 1 < NCHUNK) {
            const float4* src = (const float4*)(Kb + (size_t)(c + 1) * CHUNK * DIM);
            #pragma unroll
            for (int i = 0; i < 8; i++) pf[i] = src[i * THREADS + tid];
        }

        u64 acc[2][4];
        #pragma unroll
        for (int a = 0; a < 2; a++)
            #pragma unroll
            for (int b = 0; b < 4; b++) acc[a][b] = 0ull;

        #pragma unroll
        for (int d4 = 0; d4 < 16; d4++) {
            const int kco = (d4 ^ ksw) << 2;
            ulonglong2 kv[4];
            #pragma unroll
            for (int j = 0; j < 4; j++)
                kv[j] = *(const ulonglong2*)(Ktb + (4 * kg + j) * DIM + kco);
            const int qco = (d4 ^ qsw) << 2;
            #pragma unroll
            for (int jq = 0; jq < 2; jq++) {
                ulonglong2 qv = *(const ulonglong2*)(Qs + (2 * qg + jq) * DIM + qco);
                #pragma unroll
                for (int j = 0; j < 4; j++) {
                    ffma2(acc[jq][j], qv.x, kv[j].x);
                    ffma2(acc[jq][j], qv.y, kv[j].y);
                }
            }
        }

        const int key0 = c * CHUNK + 4 * kg;
        #pragma unroll
        for (int jq = 0; jq < 2; jq++) {
            float t[4];
            #pragma unroll
            for (int j = 0; j < 4; j++) {
                float lo, hi; upk2(acc[jq][j], lo, hi);
                float L  = (lo + hi) * scale;
                float e2 = __expf(2.0f * L);
                z1p[jq] += e2;
                t[j] = L * e2;
            }
            *(float4*)&S[(size_t)(2 * qg + jq) * NKEYS + key0] =
                make_float4(t[0], t[1], t[2], t[3]);
        }
        // no trailing barrier: next iter writes the other buffer
    }

    // ---- Z1 reduce: over the 8 kg lanes, then across the 4 matching warps ----
    #pragma unroll
    for (int jq = 0; jq < 2; jq++) {
        float v = z1p[jq];
        v += __shfl_xor_sync(0xffffffffu, v, 1);
        v += __shfl_xor_sync(0xffffffffu, v, 2);
        v += __shfl_xor_sync(0xffffffffu, v, 4);
        if ((lane & 7) == 0) zscr[warp * 8 + (lane >> 3) * 2 + jq] = v;
    }
    __syncthreads();
    if (tid < 16) {
        const int q     = tid;
        const int wbase = (q >> 3) * 4;             // warps 0-3 hold q 0-7; 4-7 hold 8-15
        const int slot  = ((q >> 1) & 3) * 2 + (q & 1);
        float z1 = 0.f;
        #pragma unroll
        for (int w = 0; w < 4; w++) z1 += zscr[(wbase + w) * 8 + slot];
        c2s[q] = 1.4426950408889634f / z1;          // log2e / Z1
    }
    __syncthreads();

    // ================= Phase 2: one conversion sweep, Z2 fused =================
    // Row cq handled by half-warp (16 threads); P = exp2(t * c2), z2 accumulated.
    const int cq = tid >> 4, cc = tid & 15;
    {
        const float c2q = c2s[cq];
        float z2 = 0.f;
        float4* p = (float4*)(S + (size_t)cq * NKEYS) + cc;
        #pragma unroll 8
        for (int i = 0; i < 32; i++) {
            float4 x = p[i * 16];
            x.x = ex2f(x.x * c2q);
            x.y = ex2f(x.y * c2q);
            x.z = ex2f(x.z * c2q);
            x.w = ex2f(x.w * c2q);
            z2 += (x.x + x.y) + (x.z + x.w);
            p[i * 16] = x;
        }
        float v = z2;
        v += __shfl_xor_sync(0xffffffffu, v, 1);
        v += __shfl_xor_sync(0xffffffffu, v, 2);
        v += __shfl_xor_sync(0xffffffffu, v, 4);
        v += __shfl_xor_sync(0xffffffffu, v, 8);
        if (cc == 0) invZ2s[cq] = 1.0f / v;
    }
    __syncthreads();   // full P' panel + invZ2s visible

    // ================= Phase 3: barrier-free O = P' V =================
    // Warp w owns keys [w*256, w*256+256), 32 blocks of 8 keys, double-buffered V.
    const int d2 = lane;                  // dcols {lane, lane+32}
    u64 acc0[MQ], acc1[MQ];
    #pragma unroll
    for (int q = 0; q < MQ; q++) { acc0[q] = 0ull; acc1[q] = 0ull; }

    const float* Vw = Vb + (size_t)(warp * 256) * DIM + d2;
    const float* Pw = S + warp * 256;
    float vA[2][8], vB[2][8];

#define LOADV(BUF, B)                                                       \
    {                                                                       \
        const float* vp = Vw + (size_t)(B) * 8 * DIM;                       \
        _Pragma("unroll")                                                   \
        for (int j = 0; j < 8; j++) {                                       \
            BUF[0][j] = vp[j * DIM];                                        \
            BUF[1][j] = vp[j * DIM + 32];                                   \
        }                                                                   \
    }

#define MMAB(BUF, B)                                                        \
    {                                                                       \
        u64 vp0[4], vp1[4];                                                 \
        _Pragma("unroll")                                                   \
        for (int j = 0; j < 4; j++) {                                       \
            vp0[j] = pk2(BUF[0][2 * j], BUF[0][2 * j + 1]);                 \
            vp1[j] = pk2(BUF[1][2 * j], BUF[1][2 * j + 1]);                 \
        }                                                                   \
        const float* pbase = Pw + (B) * 8;                                  \
        _Pragma("unroll")                                                   \
        for (int q = 0; q < MQ; q++) {                                      \
            const float* prow = pbase + (size_t)q * NKEYS;                  \
            ulonglong2 pA = *(const ulonglong2*)(prow);                     \
            ulonglong2 pB = *(const ulonglong2*)(prow + 4);                 \
            ffma2(acc0[q], pA.x, vp0[0]);                                   \
            ffma2(acc0[q], pA.y, vp0[1]);                                   \
            ffma2(acc0[q], pB.x, vp0[2]);                                   \
            ffma2(acc0[q], pB.y, vp0[3]);                                   \
            ffma2(acc1[q], pA.x, vp1[0]);                                   \
            ffma2(acc1[q], pA.y, vp1[1]);                                   \
            ffma2(acc1[q], pB.x, vp1[2]);                                   \
            ffma2(acc1[q], pB.y, vp1[3]);                                   \
        }                                                                   \
    }

    LOADV(vA, 0);
    #pragma unroll 4
    for (int b = 0; b < 32; b += 2) {
        LOADV(vB, b + 1);
        MMAB(vA, b);
        if (b + 2 < 32) LOADV(vA, b + 2);
        MMAB(vB, b + 1);
    }

    // ---- cross-warp reduction through Kt (dead): scratch[warp][q][64] ----
    float* scratch = Kt;                   // needs 8*16*64 = 8192 floats
    #pragma unroll
    for (int q = 0; q < MQ; q++) {
        float lo, hi, r0, r1;
        upk2(acc0[q], lo, hi); r0 = (lo + hi) * invZ2s[q];
        upk2(acc1[q], lo, hi); r1 = (lo + hi) * invZ2s[q];
        scratch[(warp * MQ + q) * 64 + d2]      = r0;
        scratch[(warp * MQ + q) * 64 + d2 + 32] = r1;
    }
    __syncthreads();

    #pragma unroll
    for (int e = tid; e < MQ * DIM; e += THREADS) {
        int q = e >> 6, d = e & 63;
        float r = 0.f;
        #pragma unroll
        for (int s2 = 0; s2 < 8; s2++)
            r += scratch[(s2 * MQ + q) * 64 + d];
        Ob[(size_t)q * DIM + d] = r;
    }
}

extern "C" void kernel_launch(void* const* d_in, const int* in_sizes, int n_in,
                              void* d_out, int out_size)
{
    const float* q     = (const float*)d_in[0];
    const float* k     = (const float*)d_in[1];
    const float* v     = (const float*)d_in[2];
    const float* scale = (const float*)d_in[3];
    float* out = (float*)d_out;

    cudaFuncSetAttribute(dsmax_attn_kernel,
                         cudaFuncAttributeMaxDynamicSharedMemorySize, SMEM_BYTES);

    dim3 grid(32 * NBLK_Q);   // (B*H) * query-blocks = 4096
    dsmax_attn_kernel<<<grid, THREADS, SMEM_BYTES>>>(q, k, v, scale, out);
}

// round 10
// speedup vs baseline: 1.3889x; 1.2366x over previous
#include <cuda_runtime.h>

// Double-softmax attention, fp32. B=4,H=8,N=2048,D=64.
//   L = Q K^T * scale ; mask = softmax(2L) ; attn = softmax(L*mask) ; O = attn V
// One CTA = 16 query rows of one (b,h), 256 threads.
// Warp-local staging: each warp loads/commits/computes ONLY its own K-slice
// (P1) and S-stripe (P3) -> per-chunk __syncthreads replaced by __syncwarp.
// P1: t = L*exp(2L) panel + Z1 folded.  P3: per-stripe exp2 convert + O = P V.

#define NKEYS   2048
#define DIM     64
#define MQ      16
#define CHUNK   256
#define NCHUNK  8
#define THREADS 256
#define NBLK_Q  128

#define S_FLOATS    (MQ * NKEYS)       // 32768
#define KT_FLOATS   (CHUNK * DIM)      // 16384 (K tile; P3 scratch)
#define QS_FLOATS   (MQ * DIM)         // 1024
#define SMEM_FLOATS (S_FLOATS + KT_FLOATS + QS_FLOATS + 128 + 16 + 128)
#define SMEM_BYTES  (SMEM_FLOATS * 4)  // ~197 KB

typedef unsigned long long u64;

__device__ __forceinline__ u64 pk2(float lo, float hi) {
    u64 r; asm("mov.b64 %0,{%1,%2};" : "=l"(r) : "f"(lo), "f"(hi)); return r;
}
__device__ __forceinline__ void upk2(u64 a, float& lo, float& hi) {
    asm("mov.b64 {%0,%1},%2;" : "=f"(lo), "=f"(hi) : "l"(a));
}
__device__ __forceinline__ void ffma2(u64& d, u64 a, u64 b) {
    asm("fma.rn.f32x2 %0,%1,%2,%0;" : "+l"(d) : "l"(a), "l"(b));
}
__device__ __forceinline__ float ex2f(float x) {
    float r; asm("ex2.approx.f32 %0,%1;" : "=f"(r) : "f"(x)); return r;
}

__global__ __launch_bounds__(THREADS, 1)
void dsmax_attn_kernel(const float* __restrict__ Q,
                       const float* __restrict__ K,
                       const float* __restrict__ V,
                       const float* __restrict__ scalep,
                       float* __restrict__ O)
{
    extern __shared__ float smem[];
    float* S     = smem;                      // [MQ][NKEYS]  t -> P'
    float* Kt    = S + S_FLOATS;              // [CHUNK][DIM] swizzled K / P3 scratch
    float* Qs    = Kt + KT_FLOATS;            // [MQ][DIM] swizzled Q
    float* zscr  = Qs + QS_FLOATS;            // [8 warps][16 rows] Z1 partials
    float* c2s   = zscr + 128;                // [16] log2e / Z1
    float* zscr2 = c2s + 16;                  // [8 warps][16 rows] Z2 partials

    const int tid  = threadIdx.x;
    const int warp = tid >> 5, lane = tid & 31;
    const int bh   = blockIdx.x >> 7;
    const int qb   = (blockIdx.x & (NBLK_Q - 1)) * MQ;
    const float scale = *scalep;

    const float* Qb = Q + ((size_t)bh * NKEYS + qb) * DIM;
    const float* Kb = K + (size_t)bh * NKEYS * DIM;
    const float* Vb = V + (size_t)bh * NKEYS * DIM;
    float*       Ob = O + ((size_t)bh * NKEYS + qb) * DIM;

    // ---- stage Q swizzled: col16 = d4 ^ ((q>>2)&3) ----
    {
        const int q = tid >> 4, d4 = tid & 15;
        *(float4*)&Qs[q * DIM + ((d4 ^ ((q >> 2) & 3)) << 2)] = ((const float4*)Qb)[tid];
    }

    // ---- warp-local K prefetch: warp w owns keys [32w, 32w+32) of each chunk ----
    float4 pf[16];
    const int lhi = lane >> 4;          // 0/1: key parity within pair
    const int ld4 = lane & 15;          // float4 column within key row
#define LDGK(C)                                                               \
    {                                                                         \
        const float4* src = (const float4*)(Kb + (size_t)(C) * CHUNK * DIM);  \
        _Pragma("unroll")                                                     \
        for (int i = 0; i < 16; i++)                                          \
            pf[i] = src[(size_t)(32 * warp + 2 * i + lhi) * 16 + ld4];        \
    }
    LDGK(0);
    __syncthreads();   // Qs visible to everyone

    // ================= Phase 1: t = L*exp(2L), Z1 partials =================
    // Thread tile: 4 keys x 4 q. Warp w reads ONLY Kt keys [32w, 32w+32).
    const int kg  = (tid & 7) | ((tid >> 5) << 3);   // 8*warp + (lane&7)
    const int qg  = (tid >> 3) & 3;
    const int ksw = kg & 7;
    const int qsw = qg & 3;
    float z1p[4] = {0.f, 0.f, 0.f, 0.f};

    for (int c = 0; c < NCHUNK; c++) {
        // commit own slice: key = 32*warp + 2i + lhi, swizzle (key>>2)&7 == (i>>1)&7
        #pragma unroll
        for (int i = 0; i < 16; i++) {
            const int key = 32 * warp + 2 * i + lhi;
            *(float4*)&Kt[key * DIM + ((ld4 ^ ((i >> 1) & 7)) << 2)] = pf[i];
        }
        __syncwarp();                 // slice visible to own warp
        if (c + 1 < NCHUNK) LDGK(c + 1);

        u64 acc[4][4];
        #pragma unroll
        for (int a = 0; a < 4; a++)
            #pragma unroll
            for (int b = 0; b < 4; b++) acc[a][b] = 0ull;

        #pragma unroll
        for (int d4 = 0; d4 < 16; d4++) {
            const int kco = (d4 ^ ksw) << 2;
            ulonglong2 kv[4];
            #pragma unroll
            for (int j = 0; j < 4; j++)
                kv[j] = *(const ulonglong2*)(Kt + (4 * kg + j) * DIM + kco);
            const int qco = (d4 ^ qsw) << 2;
            #pragma unroll
            for (int jq = 0; jq < 4; jq++) {
                ulonglong2 qv = *(const ulonglong2*)(Qs + (4 * qg + jq) * DIM + qco);
                #pragma unroll
                for (int j = 0; j < 4; j++) {
                    ffma2(acc[jq][j], qv.x, kv[j].x);
                    ffma2(acc[jq][j], qv.y, kv[j].y);
                }
            }
        }

        const int key0 = c * CHUNK + 4 * kg;
        #pragma unroll
        for (int jq = 0; jq < 4; jq++) {
            float t[4];
            #pragma unroll
            for (int j = 0; j < 4; j++) {
                float lo, hi; upk2(acc[jq][j], lo, hi);
                float L  = (lo + hi) * scale;
                float e2 = __expf(2.0f * L);
                z1p[jq] += e2;
                t[j] = L * e2;
            }
            *(float4*)&S[(size_t)(4 * qg + jq) * NKEYS + key0] =
                make_float4(t[0], t[1], t[2], t[3]);
        }
        __syncwarp();                 // own warp done reading slice before next commit
    }

    // ---- Z1 reduce: over the 8 kg lanes, then across warps ----
    #pragma unroll
    for (int jq = 0; jq < 4; jq++) {
        float v = z1p[jq];
        v += __shfl_xor_sync(0xffffffffu, v, 1);
        v += __shfl_xor_sync(0xffffffffu, v, 2);
        v += __shfl_xor_sync(0xffffffffu, v, 4);
        if ((lane & 7) == 0) zscr[warp * 16 + qg * 4 + jq] = v;   // slot == row
    }
    __syncthreads();
    if (tid < 16) {
        float z1 = 0.f;
        #pragma unroll
        for (int w = 0; w < 8; w++) z1 += zscr[w * 16 + tid];
        c2s[tid] = 1.4426950408889634f / z1;      // log2e / Z1
    }
    __syncthreads();

    // ================= Phase 3: warp-local convert + O = P' V =================
    // Warp w owns stripe keys [256w, 256w+256): converts it, then MMAs it.
    const int sk   = warp * 256;
    const float* Pw  = S + sk;
    const float* VwA = Vb + (size_t)sk * DIM + lane;
    const int crow = lane >> 4;         // conversion row parity
    const int ccol = lane & 15;         // conversion float4 column

    float c2r[8];
    #pragma unroll
    for (int r8 = 0; r8 < 8; r8++) c2r[r8] = c2s[2 * r8 + crow];

    u64 acc0[MQ], acc1[MQ];
    #pragma unroll
    for (int q = 0; q < MQ; q++) { acc0[q] = 0ull; acc1[q] = 0ull; }
    float z2p[8] = {0.f, 0.f, 0.f, 0.f, 0.f, 0.f, 0.f, 0.f};

    float vA[2][8], vB[2][8];

#define LOADV(BUF, B)                                                       \
    {                                                                       \
        const float* vp = VwA + (size_t)(B) * 8 * DIM;                      \
        _Pragma("unroll")                                                   \
        for (int j = 0; j < 8; j++) {                                       \
            BUF[0][j] = vp[j * DIM];                                        \
            BUF[1][j] = vp[j * DIM + 32];                                   \
        }                                                                   \
    }

#define MMAB(BUF, B)                                                        \
    {                                                                       \
        u64 vp0[4], vp1[4];                                                 \
        _Pragma("unroll")                                                   \
        for (int j = 0; j < 4; j++) {                                       \
            vp0[j] = pk2(BUF[0][2 * j], BUF[0][2 * j + 1]);                 \
            vp1[j] = pk2(BUF[1][2 * j], BUF[1][2 * j + 1]);                 \
        }                                                                   \
        const float* pbase = Pw + (B) * 8;                                  \
        _Pragma("unroll")                                                   \
        for (int q = 0; q < MQ; q++) {                                      \
            const float* prow = pbase + (size_t)q * NKEYS;                  \
            ulonglong2 pA = *(const ulonglong2*)(prow);                     \
            ulonglong2 pB = *(const ulonglong2*)(prow + 4);                 \
            ffma2(acc0[q], pA.x, vp0[0]);                                   \
            ffma2(acc0[q], pA.y, vp0[1]);                                   \
            ffma2(acc0[q], pB.x, vp0[2]);                                   \
            ffma2(acc0[q], pB.y, vp0[3]);                                   \
            ffma2(acc1[q], pA.x, vp1[0]);                                   \
            ffma2(acc1[q], pA.y, vp1[1]);                                   \
            ffma2(acc1[q], pB.x, vp1[2]);                                   \
            ffma2(acc1[q], pB.y, vp1[3]);                                   \
        }                                                                   \
    }

    LOADV(vA, 0);
    for (int g = 0; g < 4; g++) {
        // convert stripe keys [g*64, g*64+64) for all 16 rows (warp-local)
        #pragma unroll
        for (int r8 = 0; r8 < 8; r8++) {
            const int row = 2 * r8 + crow;
            float4* p = (float4*)(S + (size_t)row * NKEYS + sk + g * 64) + ccol;
            float4 x = *p;
            const float c2 = c2r[r8];
            x.x = ex2f(x.x * c2);
            x.y = ex2f(x.y * c2);
            x.z = ex2f(x.z * c2);
            x.w = ex2f(x.w * c2);
            z2p[r8] += (x.x + x.y) + (x.z + x.w);
            *p = x;
        }
        __syncwarp();                 // stripe group converted, visible to own warp
        #pragma unroll
        for (int b = 0; b < 8; b++) {
            const int B = g * 8 + b;
            if (b & 1) {
                if (B + 1 < 32) LOADV(vA, B + 1);
                MMAB(vB, B);
            } else {
                if (B + 1 < 32) LOADV(vB, B + 1);
                MMAB(vA, B);
            }
        }
    }

    // ---- Z2 stripe partials: reduce over 16-lane groups ----
    #pragma unroll
    for (int r8 = 0; r8 < 8; r8++) {
        float v = z2p[r8];
        v += __shfl_xor_sync(0xffffffffu, v, 1);
        v += __shfl_xor_sync(0xffffffffu, v, 2);
        v += __shfl_xor_sync(0xffffffffu, v, 4);
        v += __shfl_xor_sync(0xffffffffu, v, 8);
        if (ccol == 0) zscr2[warp * 16 + 2 * r8 + crow] = v;
    }

    // ---- cross-warp reduction through Kt (dead): scratch[warp][q][64] ----
    float* scratch = Kt;
    #pragma unroll
    for (int q = 0; q < MQ; q++) {
        float lo, hi;
        upk2(acc0[q], lo, hi); scratch[(warp * MQ + q) * 64 + lane]      = lo + hi;
        upk2(acc1[q], lo, hi); scratch[(warp * MQ + q) * 64 + lane + 32] = lo + hi;
    }
    __syncthreads();

    #pragma unroll
    for (int e = tid; e < MQ * DIM; e += THREADS) {
        const int q = e >> 6, d = e & 63;
        float r = 0.f, z2 = 0.f;
        #pragma unroll
        for (int w = 0; w < 8; w++) {
            r  += scratch[(w * MQ + q) * 64 + d];
            z2 += zscr2[w * 16 + q];
        }
        Ob[(size_t)q * DIM + d] = __fdividef(r, z2);
    }
}

extern "C" void kernel_launch(void* const* d_in, const int* in_sizes, int n_in,
                              void* d_out, int out_size)
{
    const float* q     = (const float*)d_in[0];
    const float* k     = (const float*)d_in[1];
    const float* v     = (const float*)d_in[2];
    const float* scale = (const float*)d_in[3];
    float* out = (float*)d_out;

    cudaFuncSetAttribute(dsmax_attn_kernel,
                         cudaFuncAttributeMaxDynamicSharedMemorySize, SMEM_BYTES);

    dim3 grid(32 * NBLK_Q);   // (B*H) * query-blocks = 4096
    dsmax_attn_kernel<<<grid, THREADS, SMEM_BYTES>>>(q, k, v, scale, out);
}